// round 16
// baseline (speedup 1.0000x reference)
#include <cuda_runtime.h>
#include <cuda_fp16.h>
#include <cstdint>
#include <cstddef>

#define HH (1024*1024)
#define WTOT ((size_t)131858432)
#define IMLO ((size_t)28311552)
#define ASLO ((size_t)16777216)
#define ZSLO ((size_t)11534336)

__device__ __half g_W [(size_t)2*WTOT];
__device__ __half g_im[(size_t)2*28311552];
__device__ __half g_As[(size_t)2*16777216];
__device__ __half g_Zs[(size_t)2*11534336];
__device__ __half g_at[(size_t)64*HH];
__device__ float  g_buf[(size_t)56*HH];

__device__ __forceinline__ void sp2(float a, float b, __half2* hi, __half2* lo)
{
    __half2 h = __floats2half2_rn(a, b);
    float2 f = __half22float2(h);
    *hi = h;
    *lo = __floats2half2_rn(a - f.x, b - f.y);
}

// ---------------- prep kernels ----------------
__global__ void transpose_split_pad(__half* dh, __half* dl, const float* src)
{
    __shared__ float tile[32][33];
    int b = blockIdx.z;
    const float* s = src + (size_t)b * 2304 * 1024;
    int c0 = blockIdx.x * 32, r0 = blockIdx.y * 32, tx = threadIdx.x, ty = threadIdx.y;
    for (int i = 0; i < 32; i += 8) tile[ty + i][tx] = s[(size_t)(r0 + ty + i) * 1024 + c0 + tx];
    __syncthreads();
    for (int i = 0; i < 32; i += 8) {
        float x = tile[tx][ty + i];
        __half h = __float2half_rn(x);
        size_t o = ((size_t)b * 1026 + 1 + c0 + ty + i) * 2304 + r0 + tx;
        dh[o] = h; dl[o] = __float2half_rn(x - __half2float(h));
    }
}

__global__ void zero_embpad(__half* dh, __half* dl)
{
    int idx = blockIdx.x * 256 + threadIdx.x;
    if (idx >= 2304) return;
    int rb = idx / 288, c8 = idx - rb * 288;
    int b = rb >> 1;
    size_t p = (size_t)b * 1026 + ((rb & 1) ? 1025 : 0);
    uint4 z = make_uint4(0, 0, 0, 0);
    *(uint4*)(dh + p * 2304 + c8 * 8) = z;
    *(uint4*)(dl + p * 2304 + c8 * 8) = z;
}

__global__ void pad_planes(__half* dh, __half* dl, const __half* sh, const __half* sl,
                           int L, int pf, int pb, int n8)
{
    int idx = blockIdx.x * 256 + threadIdx.x;
    if (idx >= n8) return;
    int p = idx >> 7, c8 = idx & 127;
    int Lp = L + pf + pb;
    int b = p / Lp, r = p - b * Lp;
    uint4 vh = make_uint4(0,0,0,0), vl = vh;
    if (r >= pf && r < L + pf) {
        size_t so = ((size_t)(b * L + r - pf) * 1024) + c8 * 8;
        vh = *(const uint4*)(sh + so);
        vl = *(const uint4*)(sl + so);
    }
    size_t o = (size_t)p * 1024 + c8 * 8;
    *(uint4*)(dh + o) = vh;
    *(uint4*)(dl + o) = vl;
}

// fused: 44 contiguous (1024,1024) weights from 4 sources -> hi planes (N,K)
__global__ void wsplit4_kernel(__half* hi, const float* s0, const float* s1,
                               const float* s2, const float* s3)
{
    __shared__ float tile[32][33];
    int z = blockIdx.z;
    const float* src; int lz;
    if (z < 16)      { src = s0; lz = z; }
    else if (z < 20) { src = s1; lz = z - 16; }
    else if (z < 32) { src = s2; lz = z - 20; }
    else             { src = s3; lz = z - 32; }
    size_t so = (size_t)lz * HH, mo = (size_t)z * HH;
    int n0 = blockIdx.x * 32, k0 = blockIdx.y * 32, tx = threadIdx.x, ty = threadIdx.y;
    for (int i = 0; i < 32; i += 8) tile[ty + i][tx] = src[so + (size_t)(k0 + ty + i) * 1024 + n0 + tx];
    __syncthreads();
    for (int i = 0; i < 32; i += 8)
        hi[mo + (size_t)(n0 + ty + i) * 1024 + k0 + tx] = __float2half_rn(tile[tx][ty + i]);
}

__global__ void wsplit_kernel(__half* hi, const float* src, int K, int N)
{
    __shared__ float tile[32][33];
    size_t mo = (size_t)blockIdx.z * K * N;
    int n0 = blockIdx.x * 32, k0 = blockIdx.y * 32, tx = threadIdx.x, ty = threadIdx.y;
    for (int i = 0; i < 32; i += 8) tile[ty + i][tx] = src[mo + (size_t)(k0 + ty + i) * N + n0 + tx];
    __syncthreads();
    for (int i = 0; i < 32; i += 8) {
        size_t o = mo + (size_t)(n0 + ty + i) * K + k0 + tx;
        hi[o] = __float2half_rn(tile[tx][ty + i]);
    }
}

__global__ void convw_split_kernel(__half* hi, const float* src, int Cin, int total)
{
    int idx = blockIdx.x * 256 + threadIdx.x;
    if (idx >= total) return;
    int K = 3 * Cin;
    int n = idx / K, r = idx - n * K;
    int ks = r / Cin, c = r - ks * Cin;
    hi[idx] = __float2half_rn(src[((size_t)n * Cin + c) * 3 + ks]);
}

__global__ void deconvw_split_kernel(__half* hi, const float* src)
{
    int idx = blockIdx.x * 256 + threadIdx.x;
    int i = blockIdx.y;
    int o = idx / 3072, r = idx - o * 3072;
    int ks = r >> 10, c = r & 1023;
    hi[(size_t)i * 3 * HH + idx] =
        __float2half_rn(src[(size_t)i * 3 * HH + ((size_t)c * 1024 + o) * 3 + ks]);
}

__global__ void deconvw_odd_kernel(__half* hi, const float* src)
{
    int idx = blockIdx.x * 256 + threadIdx.x;
    int l = blockIdx.y;
    int n = idx / 2048, k = idx - n * 2048;
    int ks = (k < 1024) ? 2 : 0;
    int c = k & 1023;
    hi[(size_t)l * 2 * HH + idx] =
        __float2half_rn(src[(size_t)l * 3 * HH + ((size_t)c * 1024 + n) * 3 + ks]);
}

__global__ void deconvw_rev_kernel(__half* hi, const float* src)
{
    int idx = blockIdx.x * 256 + threadIdx.x;
    int n = idx / 3072, k = idx - n * 3072;
    int j = k >> 10, c = k & 1023, ks = 2 - j;
    hi[idx] = __float2half_rn(src[(size_t)2 * 3 * HH + ((size_t)c * 1024 + n) * 3 + ks]);
}

// ---------------- MMA macros ----------------
#define GEMM_SM 92160
#define CP16(d, s) asm volatile("cp.async.ca.shared.global [%0], [%1], 16;" :: "r"(d), "l"(s))
#define LDSM4(r, a) asm volatile( \
    "ldmatrix.sync.aligned.m8n8.x4.shared.b16 {%0,%1,%2,%3}, [%4];" \
    : "=r"((r)[0]), "=r"((r)[1]), "=r"((r)[2]), "=r"((r)[3]) : "r"(a))
#define LDSM4T(r, a) asm volatile( \
    "ldmatrix.sync.aligned.m8n8.x4.trans.shared.b16 {%0,%1,%2,%3}, [%4];" \
    : "=r"((r)[0]), "=r"((r)[1]), "=r"((r)[2]), "=r"((r)[3]) : "r"(a))
#define MMA16(d, A_, B_) asm volatile( \
    "mma.sync.aligned.m16n8k16.row.col.f32.f16.f16.f32 " \
    "{%0,%1,%2,%3},{%4,%5,%6,%7},{%8,%9},{%0,%1,%2,%3};" \
    : "+f"((d)[0]), "+f"((d)[1]), "+f"((d)[2]), "+f"((d)[3]) \
    : "r"((A_)[0]), "r"((A_)[1]), "r"((A_)[2]), "r"((A_)[3]), "r"((B_)[0]), "r"((B_)[1]))

// ---------------- 2-term split GEMM: C = (Ah+Al) @ Bh^T, 3-stage pipe -------
__device__ __forceinline__ void gemm_body(
    const __half* Ah, const __half* Al, const __half* Bh,
    float* Cf, __half* Ch, __half* Cl, int loN,
    int M, int N, int K, int As_, int Bs_, int aBatch, int apad,
    int rowmul, int rowoff, const float* bias, int relu)
{
    extern __shared__ char smc[];
    const uint32_t smb = (uint32_t)__cvta_generic_to_shared(smc);
    const int t = threadIdx.x, lane = t & 31, wid = t >> 5;
    const int wm = wid & 1, wn = wid >> 1;
    const int bx = blockIdx.x, by = blockIdx.y;

    float acc[4][4][4];
    #pragma unroll
    for (int a = 0; a < 4; a++)
        #pragma unroll
        for (int b = 0; b < 4; b++)
            #pragma unroll
            for (int c = 0; c < 4; c++) acc[a][b][c] = 0.f;

    const __half* P[3] = {Ah, Al, Bh};
    const int KT = K >> 5;

    auto LD = [&](int s, int k0) {
        uint32_t sb = smb + (uint32_t)s * 30720u;
        #pragma unroll
        for (int p = 0; p < 2; p++) {
            #pragma unroll
            for (int i = 0; i < 2; i++) {
                int idx = i * 256 + t, r = idx >> 2, c = idx & 3;
                int g = by * 128 + r;
                int radj = aBatch ? (g + apad * (g / aBatch)) : g;
                CP16(sb + (uint32_t)p * 10240u + (uint32_t)(r * 80 + c * 16),
                     P[p] + (size_t)radj * As_ + k0 + c * 8);
            }
        }
        #pragma unroll
        for (int i = 0; i < 2; i++) {
            int idx = i * 256 + t, r = idx >> 2, c = idx & 3;
            CP16(sb + 20480u + (uint32_t)(r * 80 + c * 16),
                 P[2] + (size_t)(bx * 128 + r) * Bs_ + k0 + c * 8);
        }
    };

    auto COMP = [&](int s) {
        uint32_t sb = smb + (uint32_t)s * 30720u;
        const int arow = wm * 64 + (lane & 7) + ((lane >> 3) & 1) * 8;
        const int brow = wn * 32 + (lane & 7) + ((lane >> 4) & 1) * 8;
        #pragma unroll
        for (int kk = 0; kk < 2; kk++) {
            uint32_t ah[4][4], al[4][4], bh[4][2];
            const int achk = kk * 2 + (lane >> 4);
            const int bchk = kk * 2 + ((lane >> 3) & 1);
            #pragma unroll
            for (int mt = 0; mt < 4; mt++) {
                uint32_t ad = sb + (uint32_t)((arow + mt * 16) * 80 + achk * 16);
                LDSM4(ah[mt], ad);
                LDSM4(al[mt], ad + 10240u);
            }
            #pragma unroll
            for (int np = 0; np < 2; np++) {
                uint32_t bd = sb + 20480u + (uint32_t)((brow + np * 16) * 80 + bchk * 16);
                uint32_t r4[4];
                LDSM4(r4, bd);
                bh[np*2][0] = r4[0]; bh[np*2][1] = r4[1];
                bh[np*2+1][0] = r4[2]; bh[np*2+1][1] = r4[3];
            }
            #pragma unroll
            for (int mt = 0; mt < 4; mt++)
                #pragma unroll
                for (int nt = 0; nt < 4; nt++) {
                    MMA16(acc[mt][nt], ah[mt], bh[nt]);
                    MMA16(acc[mt][nt], al[mt], bh[nt]);
                }
        }
    };

    LD(0, 0);
    asm volatile("cp.async.commit_group;");
    if (KT > 1) {
        LD(1, 32);
        asm volatile("cp.async.commit_group;");
    }
    for (int kt = 0; kt < KT; kt++) {
        if (kt + 1 < KT) asm volatile("cp.async.wait_group 1;");
        else             asm volatile("cp.async.wait_group 0;");
        __syncthreads();
        if (kt + 2 < KT) {
            LD((kt + 2) % 3, (kt + 2) << 5);
            asm volatile("cp.async.commit_group;");
        }
        COMP(kt % 3);
    }

    const int lr = lane >> 2, lc = (lane & 3) * 2;
    #pragma unroll
    for (int mt = 0; mt < 4; mt++) {
        int r0 = by * 128 + wm * 64 + mt * 16 + lr;
        int g0 = rowmul * r0 + rowoff;
        int g1 = rowmul * (r0 + 8) + rowoff;
        #pragma unroll
        for (int nt = 0; nt < 4; nt++) {
            int c0 = bx * 128 + wn * 32 + nt * 8 + lc;
            float b0 = 0.f, b1 = 0.f;
            if (bias) { float2 bv = *(const float2*)(bias + c0); b0 = bv.x; b1 = bv.y; }
            float v0 = acc[mt][nt][0] + b0, v1 = acc[mt][nt][1] + b1;
            float v2 = acc[mt][nt][2] + b0, v3 = acc[mt][nt][3] + b1;
            if (relu) { v0 = fmaxf(v0,0.f); v1 = fmaxf(v1,0.f);
                        v2 = fmaxf(v2,0.f); v3 = fmaxf(v3,0.f); }
            size_t o0 = (size_t)g0 * N + c0, o1 = (size_t)g1 * N + c0;
            if (Cf) {
                *(float2*)(Cf + o0) = make_float2(v0, v1);
                *(float2*)(Cf + o1) = make_float2(v2, v3);
            }
            if (Ch) {
                __half2 hh, ll;
                sp2(v0, v1, &hh, &ll);
                *(__half2*)(Ch + o0) = hh;
                if (c0 < loN) *(__half2*)(Cl + o0) = ll;
                sp2(v2, v3, &hh, &ll);
                *(__half2*)(Ch + o1) = hh;
                if (c0 < loN) *(__half2*)(Cl + o1) = ll;
            }
        }
    }
}

__global__ __launch_bounds__(256) void gemm_fp16(
    const __half* Ah, const __half* Al, const __half* Bh,
    float* Cf, __half* Ch, __half* Cl, int loN,
    int M, int N, int K, int As_, int Bs_, int aBatch, int apad,
    int rowmul, int rowoff, const float* bias, int relu)
{
    gemm_body(Ah, Al, Bh, Cf, Ch, Cl, loN, M, N, K, As_, Bs_, aBatch, apad,
              rowmul, rowoff, bias, relu);
}

__global__ __launch_bounds__(256) void gemm_dual(
    const __half* A0h, const __half* A0l, const __half* B0h,
    float* C0f, __half* C0h, __half* C0l, int loN0,
    const __half* A1h, const __half* A1l, const __half* B1h,
    float* C1f, __half* C1h, __half* C1l, int loN1,
    int M, int N, int K)
{
    if (blockIdx.z == 0)
        gemm_body(A0h, A0l, B0h, C0f, C0h, C0l, loN0, M, N, K, K, K, 0, 0, 1, 0, nullptr, 0);
    else
        gemm_body(A1h, A1l, B1h, C1f, C1h, C1l, loN1, M, N, K, K, K, 0, 0, 1, 0, nullptr, 0);
}

// ---------------- flash attention: Q exact, K/V fp16-hi, P exact ----------
#define AT_SM 110592
__device__ __forceinline__ void attn_body(
    const __half* Qh, const __half* Ql, const __half* Kh, const __half* Vh,
    __half* Oh, __half* Ol,
    int S, int windowed, int qstr, int kstr, int qb, int h, int b)
{
    extern __shared__ char smc[];
    const uint32_t sb = (uint32_t)__cvta_generic_to_shared(smc);
    const int t = threadIdx.x, lane = t & 31, w = t >> 5;
    const int lr = lane >> 2, lc = lane & 3;
    const size_t qbase = (size_t)(b * S + qb * 128) * qstr + h * 64;
    const size_t obase = (size_t)(b * S + qb * 128) * 1024 + h * 64;

    for (int i = t; i < 1024; i += 256) {
        int r = i >> 3, c = i & 7;
        size_t go = qbase + (size_t)r * qstr + c * 8;
        uint32_t so = (uint32_t)(r * 144 + c * 16);
        CP16(sb + so,          Qh + go);
        CP16(sb + 18432u + so, Ql + go);
    }
    asm volatile("cp.async.commit_group;");

    const int nb = windowed ? 1 : (S >> 7);
    const int jb0 = windowed ? qb : 0;

    auto ldkv = [&](int jb, int st) {
        uint32_t kb = sb + 36864u + (uint32_t)st * 36864u;
        size_t gb = (size_t)(b * S + jb * 128) * kstr + h * 64;
        for (int i = t; i < 1024; i += 256) {
            int r = i >> 3, c = i & 7;
            size_t go = gb + (size_t)r * kstr + c * 8;
            uint32_t so = (uint32_t)(r * 144 + c * 16);
            CP16(kb + so,           Kh + go);
            CP16(kb + 18432u + so,  Vh + go);
        }
    };

    ldkv(jb0, 0);
    asm volatile("cp.async.commit_group;");
    asm volatile("cp.async.wait_group 1;");
    __syncthreads();

    uint32_t qfh[4][4], qfl[4][4];
    {
        uint32_t qrow = (uint32_t)(w * 16 + (lane & 7) + ((lane >> 3) & 1) * 8);
        #pragma unroll
        for (int kc = 0; kc < 4; kc++) {
            uint32_t qa = sb + qrow * 144u + (uint32_t)((kc * 2 + (lane >> 4)) * 16);
            LDSM4(qfh[kc], qa);
            LDSM4(qfl[kc], qa + 18432u);
        }
    }

    float oacc[8][4];
    #pragma unroll
    for (int j = 0; j < 8; j++)
        #pragma unroll
        for (int c = 0; c < 4; c++) oacc[j][c] = 0.f;
    float m0 = -1e30f, m1 = -1e30f, l0 = 0.f, l1 = 0.f;

    for (int i = 0; i < nb; i++) {
        if (i + 1 < nb) {
            ldkv(jb0 + i + 1, (i + 1) & 1);
            asm volatile("cp.async.commit_group;");
            asm volatile("cp.async.wait_group 1;");
        } else {
            asm volatile("cp.async.wait_group 0;");
        }
        __syncthreads();
        uint32_t kb = sb + 36864u + (uint32_t)(i & 1) * 36864u;

        float sacc[16][4];
        #pragma unroll
        for (int nt = 0; nt < 16; nt++)
            #pragma unroll
            for (int c = 0; c < 4; c++) sacc[nt][c] = 0.f;

        const uint32_t krow = (uint32_t)((lane & 7) + ((lane >> 4) & 1) * 8);
        const uint32_t kchk = (uint32_t)((lane >> 3) & 1);
        #pragma unroll
        for (int np = 0; np < 8; np++) {
            #pragma unroll
            for (int kc = 0; kc < 4; kc++) {
                uint32_t ka = kb + (np * 16 + krow) * 144u + (kc * 2 + kchk) * 16u;
                uint32_t bh4[4];
                LDSM4(bh4, ka);
                MMA16(sacc[2*np],   qfh[kc], &bh4[0]);
                MMA16(sacc[2*np],   qfl[kc], &bh4[0]);
                MMA16(sacc[2*np+1], qfh[kc], &bh4[2]);
                MMA16(sacc[2*np+1], qfl[kc], &bh4[2]);
            }
        }

        float mx0 = -1e30f, mx1 = -1e30f;
        #pragma unroll
        for (int nt = 0; nt < 16; nt++) {
            sacc[nt][0] *= 0.125f; sacc[nt][1] *= 0.125f;
            sacc[nt][2] *= 0.125f; sacc[nt][3] *= 0.125f;
            mx0 = fmaxf(mx0, fmaxf(sacc[nt][0], sacc[nt][1]));
            mx1 = fmaxf(mx1, fmaxf(sacc[nt][2], sacc[nt][3]));
        }
        mx0 = fmaxf(mx0, __shfl_xor_sync(0xffffffffu, mx0, 1));
        mx0 = fmaxf(mx0, __shfl_xor_sync(0xffffffffu, mx0, 2));
        mx1 = fmaxf(mx1, __shfl_xor_sync(0xffffffffu, mx1, 1));
        mx1 = fmaxf(mx1, __shfl_xor_sync(0xffffffffu, mx1, 2));
        float nm0 = fmaxf(m0, mx0), nm1 = fmaxf(m1, mx1);
        float cr0 = __expf(m0 - nm0), cr1 = __expf(m1 - nm1);
        l0 *= cr0; l1 *= cr1;
        #pragma unroll
        for (int j = 0; j < 8; j++) {
            oacc[j][0] *= cr0; oacc[j][1] *= cr0;
            oacc[j][2] *= cr1; oacc[j][3] *= cr1;
        }
        float rs0 = 0.f, rs1 = 0.f;
        #pragma unroll
        for (int nt = 0; nt < 16; nt++) {
            float p0 = __expf(sacc[nt][0] - nm0), p1 = __expf(sacc[nt][1] - nm0);
            float p2 = __expf(sacc[nt][2] - nm1), p3 = __expf(sacc[nt][3] - nm1);
            sacc[nt][0] = p0; sacc[nt][1] = p1; sacc[nt][2] = p2; sacc[nt][3] = p3;
            rs0 += p0 + p1; rs1 += p2 + p3;
        }
        rs0 += __shfl_xor_sync(0xffffffffu, rs0, 1);
        rs0 += __shfl_xor_sync(0xffffffffu, rs0, 2);
        rs1 += __shfl_xor_sync(0xffffffffu, rs1, 1);
        rs1 += __shfl_xor_sync(0xffffffffu, rs1, 2);
        l0 += rs0; l1 += rs1; m0 = nm0; m1 = nm1;

        const uint32_t vrow = (uint32_t)((lane & 7) + ((lane >> 3) & 1) * 8);
        const uint32_t vchk = (uint32_t)((lane >> 4) & 1);
        #pragma unroll
        for (int kc = 0; kc < 8; kc++) {
            uint32_t ph[4], pl[4];
            #pragma unroll
            for (int q = 0; q < 2; q++) {
                __half2 hh, ll;
                sp2(sacc[2*kc+q][0], sacc[2*kc+q][1], &hh, &ll);
                ph[q*2]   = *(uint32_t*)&hh; pl[q*2]   = *(uint32_t*)&ll;
                sp2(sacc[2*kc+q][2], sacc[2*kc+q][3], &hh, &ll);
                ph[q*2+1] = *(uint32_t*)&hh; pl[q*2+1] = *(uint32_t*)&ll;
            }
            #pragma unroll
            for (int p4 = 0; p4 < 4; p4++) {
                uint32_t va = kb + 18432u + (kc * 16 + vrow) * 144u + p4 * 32u + vchk * 16u;
                uint32_t vh4[4];
                LDSM4T(vh4, va);
                MMA16(oacc[2*p4],   ph, &vh4[0]);
                MMA16(oacc[2*p4],   pl, &vh4[0]);
                MMA16(oacc[2*p4+1], ph, &vh4[2]);
                MMA16(oacc[2*p4+1], pl, &vh4[2]);
            }
        }
        __syncthreads();
    }

    const float i0 = 1.f / l0, i1 = 1.f / l1;
    #pragma unroll
    for (int j = 0; j < 8; j++) {
        size_t o0 = obase + (size_t)(w * 16 + lr) * 1024 + j * 8 + lc * 2;
        __half2 hh, ll;
        sp2(oacc[j][0] * i0, oacc[j][1] * i0, &hh, &ll);
        *(__half2*)(Oh + o0) = hh; *(__half2*)(Ol + o0) = ll;
        sp2(oacc[j][2] * i1, oacc[j][3] * i1, &hh, &ll);
        *(__half2*)(Oh + o0 + 8192) = hh; *(__half2*)(Ol + o0 + 8192) = ll;
    }
}

__global__ __launch_bounds__(256) void attn_tc(
    const __half* Qh, const __half* Ql, const __half* Kh, const __half* Vh,
    __half* Oh, __half* Ol, int S, int windowed, int qstr, int kstr)
{
    attn_body(Qh, Ql, Kh, Vh, Oh, Ol, S, windowed, qstr, kstr,
              blockIdx.x, blockIdx.y, blockIdx.z);
}

__global__ __launch_bounds__(256) void attn_tc_dual(
    const __half* Q0h, const __half* Q0l, const __half* K0h, const __half* V0h,
    __half* O0h, __half* O0l,
    const __half* Q1h, const __half* Q1l, const __half* K1h, const __half* V1h,
    __half* O1h, __half* O1l, int S)
{
    int b = blockIdx.z & 3;
    if ((blockIdx.z >> 2) == 0)
        attn_body(Q0h, Q0l, K0h, V0h, O0h, O0l, S, 0, 1024, 2048,
                  blockIdx.x, blockIdx.y, b);
    else
        attn_body(Q1h, Q1l, K1h, V1h, O1h, O1l, S, 0, 1024, 2048,
                  blockIdx.x, blockIdx.y, b);
}

// ---------------- ln / ln_add / pool ----------------
__device__ __forceinline__ float4 ln_row(const float* in1, const float* in2,
                                         const float* g, const float* be,
                                         size_t base, int tid, float* rs, float* rss)
{
    float4 a = *(const float4*)(in1 + base), b2 = *(const float4*)(in2 + base);
    a.x += b2.x; a.y += b2.y; a.z += b2.z; a.w += b2.w;
    float s = a.x + a.y + a.z + a.w;
    float ss = a.x*a.x + a.y*a.y + a.z*a.z + a.w*a.w;
    for (int o = 16; o > 0; o >>= 1) {
        s += __shfl_xor_sync(0xffffffffu, s, o);
        ss += __shfl_xor_sync(0xffffffffu, ss, o);
    }
    if ((tid & 31) == 0) { rs[tid >> 5] = s; rss[tid >> 5] = ss; }
    __syncthreads();
    float st = 0.f, sst = 0.f;
    for (int i = 0; i < 8; i++) { st += rs[i]; sst += rss[i]; }
    const float mean = st * (1.f/1024.f), var = sst * (1.f/1024.f) - mean*mean;
    const float inv = rsqrtf(var + 1e-5f);
    float4 gg = *(const float4*)(g + tid*4), bb = *(const float4*)(be + tid*4), o4;
    o4.x = (a.x-mean)*inv*gg.x + bb.x; o4.y = (a.y-mean)*inv*gg.y + bb.y;
    o4.z = (a.z-mean)*inv*gg.z + bb.z; o4.w = (a.w-mean)*inv*gg.w + bb.w;
    return o4;
}

__global__ __launch_bounds__(256) void ln_kernel(
    float* out, const float* in1, const float* in2, const float* g, const float* be,
    __half* ph, __half* pl)
{
    __shared__ float rs[8], rss[8];
    const int tid = threadIdx.x;
    const size_t base = (size_t)blockIdx.x * 1024 + tid * 4;
    float4 o4 = ln_row(in1, in2, g, be, base, tid, rs, rss);
    *(float4*)(out + base) = o4;
    if (ph) {
        __half2 hh, ll;
        sp2(o4.x, o4.y, &hh, &ll);
        *(__half2*)(ph + base) = hh; *(__half2*)(pl + base) = ll;
        sp2(o4.z, o4.w, &hh, &ll);
        *(__half2*)(ph + base + 2) = hh; *(__half2*)(pl + base + 2) = ll;
    }
}

__global__ __launch_bounds__(256) void ln_add_dual(
    float* out, __half* ph, __half* pl,
    const float* fe, const float* bT, const float* g0, const float* e0,
    const float* fd, const float* bT2, const float* g1, const float* e1)
{
    __shared__ float rs[8], rss[8];
    const int tid = threadIdx.x;
    const size_t base = (size_t)blockIdx.x * 1024 + tid * 4;
    float4 x2 = ln_row(fe, bT, g0, e0, base, tid, rs, rss);
    __syncthreads();
    float4 y2 = ln_row(fd, bT2, g1, e1, base, tid, rs, rss);
    float4 o4 = make_float4(x2.x + y2.x, x2.y + y2.y, x2.z + y2.z, x2.w + y2.w);
    *(float4*)(out + base) = o4;
    __half2 hh, ll;
    sp2(o4.x, o4.y, &hh, &ll);
    *(__half2*)(ph + base) = hh; *(__half2*)(pl + base) = ll;
    sp2(o4.z, o4.w, &hh, &ll);
    *(__half2*)(ph + base + 2) = hh; *(__half2*)(pl + base + 2) = ll;
}

__global__ void poolrelu_kernel(float* out, __half* ph, __half* pl,
                                const float* in, int S2, int n4)
{
    int idx = blockIdx.x * blockDim.x + threadIdx.x;
    if (idx >= n4) return;
    int h4 = idx & 255, bt = idx >> 8, b = bt / S2, t2 = bt - b * S2;
    const float4* i0 = (const float4*)in + ((size_t)(b*S2*2 + t2*2) * 256 + h4);
    float4 a = i0[0], c = i0[256], o;
    o.x = fmaxf(fmaxf(a.x,c.x),0.f); o.y = fmaxf(fmaxf(a.y,c.y),0.f);
    o.z = fmaxf(fmaxf(a.z,c.z),0.f); o.w = fmaxf(fmaxf(a.w,c.w),0.f);
    ((float4*)out)[idx] = o;
    size_t base = (size_t)idx * 4;
    __half2 hh, ll;
    sp2(o.x, o.y, &hh, &ll);
    *(__half2*)(ph + base) = hh; *(__half2*)(pl + base) = ll;
    sp2(o.z, o.w, &hh, &ll);
    *(__half2*)(ph + base + 2) = hh; *(__half2*)(pl + base + 2) = ll;
}

// ---------------- host ----------------
extern "C" void kernel_launch(void* const* d_in, const int* in_sizes, int n_in,
                              void* d_out, int out_size)
{
    (void)in_sizes; (void)n_in; (void)out_size;
    const float* x        = (const float*)d_in[0];
    const float* emb_w    = (const float*)d_in[1];
    const float* emb_b    = (const float*)d_in[2];
    const float* enc_qkvo = (const float*)d_in[3];
    const float* enc_ln   = (const float*)d_in[4];
    const float* ef1      = (const float*)d_in[5];
    const float* eb1      = (const float*)d_in[6];
    const float* ef2      = (const float*)d_in[7];
    const float* eb2      = (const float*)d_in[8];
    const float* conv0_w  = (const float*)d_in[9];
    const float* conv0_b  = (const float*)d_in[10];
    const float* dq0      = (const float*)d_in[11];
    const float* dln0     = (const float*)d_in[12];
    const float* da1      = (const float*)d_in[13];
    const float* da2      = (const float*)d_in[14];
    const float* dln      = (const float*)d_in[15];
    const float* df1      = (const float*)d_in[16];
    const float* db1      = (const float*)d_in[17];
    const float* df2      = (const float*)d_in[18];
    const float* db2      = (const float*)d_in[19];
    const float* ddw      = (const float*)d_in[20];
    const float* ddb      = (const float*)d_in[21];

    __half *W, *im, *As, *Zs, *at;
    float *buf;
    cudaGetSymbolAddress((void**)&W,  g_W);
    cudaGetSymbolAddress((void**)&im, g_im);
    cudaGetSymbolAddress((void**)&As, g_As);
    cudaGetSymbolAddress((void**)&Zs, g_Zs);
    cudaGetSymbolAddress((void**)&at, g_at);
    cudaGetSymbolAddress((void**)&buf, g_buf);

    float *bX = buf, *bT = buf+(size_t)20*HH, *bY = buf+(size_t)24*HH,
          *bD = buf+(size_t)28*HH, *bZ = buf+(size_t)36*HH, *bT2 = buf+(size_t)40*HH;
    __half *Ash = As, *Asl = As + ASLO, *imL = im + IMLO;
    __half *Zsh = Zs, *Zsl = Zs + ZSLO;
    __half *fdph = im + (size_t)20*HH, *fdpl = im + IMLO + (size_t)20*HH;
    __half *Q0h = at,                 *Q0l = at + (size_t)4*HH,
           *KV0h = at + (size_t)8*HH,  *KV0l = at + (size_t)16*HH,
           *A0h = at + (size_t)24*HH,  *A0l = at + (size_t)28*HH,
           *Q1h = at + (size_t)32*HH,  *Q1l = at + (size_t)36*HH,
           *KV1h = at + (size_t)40*HH, *KV1l = at + (size_t)48*HH,
           *A1h = at + (size_t)56*HH,  *A1l = at + (size_t)60*HH;
    __half *QKVh = at, *QKVl = at + (size_t)12*HH;

    const size_t oE = 0, oD0 = (size_t)16*HH, oD1 = (size_t)20*HH, oD2 = (size_t)32*HH,
                 oF1e = (size_t)44*HH, oF2e = (size_t)60*HH, oF1d = (size_t)76*HH,
                 oF2d = (size_t)88*HH, oWe = (size_t)100*HH,
                 oWc = oWe + 7077888, oWd = oWc + (size_t)3*HH,
                 oWdO = oWd + (size_t)9*HH, oWdR = oWdO + (size_t)4*HH;
    const size_t zo[4] = {0, 4194304, 8388608, 10485760};

    float* out = (float*)d_out;
    float* Z0 = out;                      float* Z1 = out + (size_t)4194304;
    float* Z2 = out + (size_t)8388608;    float* Z3 = out + (size_t)10485760;
    float* FD0 = out + (size_t)11534336;  float* FD1 = out + (size_t)12582912;
    float* FD2 = out + (size_t)14680064;  float* FD3 = out + (size_t)18874368;

    cudaFuncSetAttribute(attn_tc, cudaFuncAttributeMaxDynamicSharedMemorySize, AT_SM);
    cudaFuncSetAttribute(attn_tc_dual, cudaFuncAttributeMaxDynamicSharedMemorySize, AT_SM);
    cudaFuncSetAttribute(gemm_fp16, cudaFuncAttributeMaxDynamicSharedMemorySize, GEMM_SM);
    cudaFuncSetAttribute(gemm_dual, cudaFuncAttributeMaxDynamicSharedMemorySize, GEMM_SM);

    auto GE = [&](const __half* ah, const __half* al, size_t ow,
                  float* Cf, __half* Ch, __half* Cl, int loN,
                  int M, int N, int K, const float* bias, int relu) {
        gemm_fp16<<<dim3(N/128, M/128), 256, GEMM_SM>>>(ah, al, W + ow,
            Cf, Ch, Cl, loN, M, N, K, K, K, 0, 0, 1, 0, bias, relu);
    };
    auto GEc = [&](const __half* ah, const __half* al, int As_, int aB, int apad,
                   size_t bo, int Bs_, float* Cf, __half* Ch, __half* Cl,
                   int M, int N, int K, int rm, int ro, const float* bias, int relu) {
        gemm_fp16<<<dim3(N/128, M/128), 256, GEMM_SM>>>(ah, al, W + bo,
            Cf, Ch, Cl, N, M, N, K, As_, Bs_, aB, apad, rm, ro, bias, relu);
    };
    auto GE2 = [&](const __half* a0h, const __half* a0l, size_t w0,
                   float* c0f, __half* c0h, __half* c0l, int loN0,
                   const __half* a1h, const __half* a1l, size_t w1,
                   float* c1f, __half* c1h, __half* c1l, int loN1,
                   int M, int N, int K) {
        gemm_dual<<<dim3(N/128, M/128, 2), 256, GEMM_SM>>>(
            a0h, a0l, W + w0, c0f, c0h, c0l, loN0,
            a1h, a1l, W + w1, c1f, c1h, c1l, loN1, M, N, K);
    };

    // ---- prep ----
    dim3 b32(32, 8);
    transpose_split_pad<<<dim3(32, 72, 4), b32>>>(im, imL, x);
    zero_embpad<<<9, 256>>>(im, imL);
    convw_split_kernel<<<27648, 256>>>(W + oWe, emb_w, 2304, 7077888);
    wsplit4_kernel<<<dim3(32, 32, 44), b32>>>(W + oE, enc_qkvo, dq0, da1, da2);
    wsplit_kernel<<<dim3(128, 32, 4), b32>>>(W + oF1e, ef1, 1024, 4096);
    wsplit_kernel<<<dim3(32, 128, 4), b32>>>(W + oF2e, ef2, 4096, 1024);
    wsplit_kernel<<<dim3(128, 32, 3), b32>>>(W + oF1d, df1, 1024, 4096);
    wsplit_kernel<<<dim3(32, 128, 3), b32>>>(W + oF2d, df2, 4096, 1024);
    convw_split_kernel<<<12288, 256>>>(W + oWc, conv0_w, 1024, 3*HH);
    deconvw_split_kernel<<<dim3(12288, 3), 256>>>(W + oWd, ddw);
    deconvw_odd_kernel<<<dim3(8192, 2), 256>>>(W + oWdO, ddw);
    deconvw_rev_kernel<<<12288, 256>>>(W + oWdR, ddw);

    GEc(im, imL, 2304, 1024, 2, oWe, 6912, bX, Ash, Asl, 4096, 1024, 6912, 1, 0, emb_b, 1);

    auto mhaSelf = [&](const __half* xh, const __half* xl, size_t ow, int S, int wnd) {
        int rows = 4 * S;
        GE(xh, xl, ow, nullptr, QKVh, QKVl, 1024, rows, 3072, 1024, nullptr, 0);
        attn_tc<<<dim3(S/128, 16, 4), 256, AT_SM>>>(
            QKVh, QKVl, QKVh + 1024, QKVh + 2048,
            A0h, A0l, S, wnd, 3072, 3072);
        GE(A0h, A0l, ow + (size_t)3*HH, bT, nullptr, nullptr, 0, rows, 1024, 1024, nullptr, 0);
    };

    const int encS[4] = {1024, 1024, 512, 256};
    float* Zp[4] = {Z0, Z1, Z2, Z3};
    for (int i = 0; i < 4; i++) {
        int S = encS[i], rows = 4 * S;
        mhaSelf(Ash, Asl, oE + (size_t)i*4*HH, S, 1);
        const float* lnb = enc_ln + (size_t)i * 4096;
        ln_kernel<<<rows, 256>>>(bY, bX, bT, lnb, lnb + 1024, Ash, Asl);
        GE(Ash, Asl, oF1e + (size_t)i*4*HH, nullptr, im, imL, 4096, rows, 4096, 1024,
           eb1 + (size_t)i*4096, 1);
        GE(im, imL, oF2e + (size_t)i*4*HH, bT, nullptr, nullptr, 0, rows, 1024, 4096,
           eb2 + (size_t)i*1024, 0);
        ln_kernel<<<rows, 256>>>(Zp[i], bY, bT, lnb + 2048, lnb + 3072,
                                 Zsh + zo[i], Zsl + zo[i]);
        if (i == 0) {
            pad_planes<<<(4*1026*128 + 255)/256, 256>>>(im, imL, Zsh + zo[0], Zsl + zo[0],
                                                        1024, 1, 1, 4*1026*128);
            GEc(im, imL, 1024, 1024, 2, oWc, 3072, bX, Ash, Asl, rows, 1024, 3072, 1, 0,
                conv0_b, 1);
        } else if (i < 3) {
            int S2 = S/2, n4 = 4*S2*256;
            poolrelu_kernel<<<(n4 + 255)/256, 256>>>(bX, Ash, Asl, Zp[i], S2, n4);
        }
    }

    mhaSelf(Zsh + zo[3], Zsl + zo[3], oD0, 256, 0);
    ln_kernel<<<1024, 256>>>(FD0, Z3, bT, dln0, dln0 + 1024, fdph, fdpl);

    const float* fdPrev = FD0; int Sprev = 256;
    const float* feP[3] = {Z2, Z1, Z0};
    const size_t feZ[3] = {zo[2], zo[1], zo[0]};
    const int decS[3] = {512, 1024, 1024}, decSt[3] = {2, 2, 1};
    float* fdOut[3] = {FD1, FD2, FD3};
    for (int i = 0; i < 3; i++) {
        int S = decS[i], rows = 4 * S;
        if (decSt[i] == 2) {
            int n8 = 4*(Sprev+1)*128;
            pad_planes<<<(n8 + 255)/256, 256>>>(im, imL, fdph, fdpl, Sprev, 0, 1, n8);
            GEc(fdph, fdpl, 1024, 0, 0, oWd + (size_t)i*3*HH + 1024, 3072,
                bD, Ash, Asl, rows/2, 1024, 1024, 2, 0, ddb + (size_t)i*1024, 1);
            GEc(im, imL, 1024, Sprev, 1, oWdO + (size_t)i*2*HH, 2048,
                bD, Ash, Asl, rows/2, 1024, 2048, 2, 1, ddb + (size_t)i*1024, 1);
        } else {
            int n8 = 4*(Sprev+2)*128;
            pad_planes<<<(n8 + 255)/256, 256>>>(im, imL, fdph, fdpl, Sprev, 1, 1, n8);
            GEc(im, imL, 1024, 1024, 2, oWdR, 3072,
                bD, Ash, Asl, rows, 1024, 3072, 1, 0, ddb + (size_t)i*1024, 1);
        }
        const float* lnb = dln + (size_t)i * 6144;
        const size_t a1 = oD1 + (size_t)i*4*HH, a2 = oD2 + (size_t)i*4*HH;
        GE2(Zsh + feZ[i], Zsl + feZ[i], a1, nullptr, Q0h, Q0l, 1024,
            Ash, Asl,                   a2, nullptr, Q1h, Q1l, 1024, rows, 1024, 1024);
        GE2(Ash, Asl,                   a1 + (size_t)HH, nullptr, KV0h, KV0l, 0,
            Zsh + feZ[i], Zsl + feZ[i], a2 + (size_t)HH, nullptr, KV1h, KV1l, 0,
            rows, 2048, 1024);
        attn_tc_dual<<<dim3(S/128, 16, 8), 256, AT_SM>>>(
            Q0h, Q0l, KV0h, KV0h + 1024, A0h, A0l,
            Q1h, Q1l, KV1h, KV1h + 1024, A1h, A1l, S);
        GE2(A0h, A0l, a1 + (size_t)3*HH, bT,  nullptr, nullptr, 0,
            A1h, A1l, a2 + (size_t)3*HH, bT2, nullptr, nullptr, 0, rows, 1024, 1024);
        ln_add_dual<<<rows, 256>>>(bZ, Ash, Asl, feP[i], bT, lnb, lnb + 1024,
                                   bD, bT2, lnb + 2048, lnb + 3072);
        GE(Ash, Asl, oF1d + (size_t)i*4*HH, nullptr, im, imL, 4096, rows, 4096, 1024,
           db1 + (size_t)i*4096, 1);
        GE(im, imL, oF2d + (size_t)i*4*HH, bT, nullptr, nullptr, 0, rows, 1024, 4096,
           db2 + (size_t)i*1024, 0);
        ln_kernel<<<rows, 256>>>(fdOut[i], bZ, bT, lnb + 4096, lnb + 5120, fdph, fdpl);
        fdPrev = fdOut[i]; Sprev = S;
    }
    (void)fdPrev;
}

// round 17
// speedup vs baseline: 1.0303x; 1.0303x over previous
#include <cuda_runtime.h>
#include <cuda_fp16.h>
#include <cstdint>
#include <cstddef>

#define HH (1024*1024)
#define WTOT ((size_t)131858432)
#define IMLO ((size_t)28311552)
#define ASLO ((size_t)16777216)
#define ZSLO ((size_t)11534336)

__device__ __half g_W [(size_t)2*WTOT];
__device__ __half g_im[(size_t)2*28311552];
__device__ __half g_As[(size_t)2*16777216];
__device__ __half g_Zs[(size_t)2*11534336];
__device__ __half g_at[(size_t)64*HH];
__device__ float  g_buf[(size_t)56*HH];

__device__ __forceinline__ void sp2(float a, float b, __half2* hi, __half2* lo)
{
    __half2 h = __floats2half2_rn(a, b);
    float2 f = __half22float2(h);
    *hi = h;
    *lo = __floats2half2_rn(a - f.x, b - f.y);
}

// ---------------- prep kernels ----------------
__global__ void transpose_split_pad(__half* dh, __half* dl, const float* src)
{
    __shared__ float tile[32][33];
    int b = blockIdx.z;
    const float* s = src + (size_t)b * 2304 * 1024;
    int c0 = blockIdx.x * 32, r0 = blockIdx.y * 32, tx = threadIdx.x, ty = threadIdx.y;
    for (int i = 0; i < 32; i += 8) tile[ty + i][tx] = s[(size_t)(r0 + ty + i) * 1024 + c0 + tx];
    __syncthreads();
    for (int i = 0; i < 32; i += 8) {
        float x = tile[tx][ty + i];
        __half h = __float2half_rn(x);
        size_t o = ((size_t)b * 1026 + 1 + c0 + ty + i) * 2304 + r0 + tx;
        dh[o] = h; dl[o] = __float2half_rn(x - __half2float(h));
    }
}

__global__ void zero_embpad(__half* dh, __half* dl)
{
    int idx = blockIdx.x * 256 + threadIdx.x;
    if (idx >= 2304) return;
    int rb = idx / 288, c8 = idx - rb * 288;
    int b = rb >> 1;
    size_t p = (size_t)b * 1026 + ((rb & 1) ? 1025 : 0);
    uint4 z = make_uint4(0, 0, 0, 0);
    *(uint4*)(dh + p * 2304 + c8 * 8) = z;
    *(uint4*)(dl + p * 2304 + c8 * 8) = z;
}

__global__ void pad_planes(__half* dh, __half* dl, const __half* sh, const __half* sl,
                           int L, int pf, int pb, int n8)
{
    int idx = blockIdx.x * 256 + threadIdx.x;
    if (idx >= n8) return;
    int p = idx >> 7, c8 = idx & 127;
    int Lp = L + pf + pb;
    int b = p / Lp, r = p - b * Lp;
    uint4 vh = make_uint4(0,0,0,0), vl = vh;
    if (r >= pf && r < L + pf) {
        size_t so = ((size_t)(b * L + r - pf) * 1024) + c8 * 8;
        vh = *(const uint4*)(sh + so);
        vl = *(const uint4*)(sl + so);
    }
    size_t o = (size_t)p * 1024 + c8 * 8;
    *(uint4*)(dh + o) = vh;
    *(uint4*)(dl + o) = vl;
}

__global__ void wsplit4_kernel(__half* hi, const float* s0, const float* s1,
                               const float* s2, const float* s3)
{
    __shared__ float tile[32][33];
    int z = blockIdx.z;
    const float* src; int lz;
    if (z < 16)      { src = s0; lz = z; }
    else if (z < 20) { src = s1; lz = z - 16; }
    else if (z < 32) { src = s2; lz = z - 20; }
    else             { src = s3; lz = z - 32; }
    size_t so = (size_t)lz * HH, mo = (size_t)z * HH;
    int n0 = blockIdx.x * 32, k0 = blockIdx.y * 32, tx = threadIdx.x, ty = threadIdx.y;
    for (int i = 0; i < 32; i += 8) tile[ty + i][tx] = src[so + (size_t)(k0 + ty + i) * 1024 + n0 + tx];
    __syncthreads();
    for (int i = 0; i < 32; i += 8)
        hi[mo + (size_t)(n0 + ty + i) * 1024 + k0 + tx] = __float2half_rn(tile[tx][ty + i]);
}

__global__ void wsplit_kernel(__half* hi, const float* src, int K, int N)
{
    __shared__ float tile[32][33];
    size_t mo = (size_t)blockIdx.z * K * N;
    int n0 = blockIdx.x * 32, k0 = blockIdx.y * 32, tx = threadIdx.x, ty = threadIdx.y;
    for (int i = 0; i < 32; i += 8) tile[ty + i][tx] = src[mo + (size_t)(k0 + ty + i) * N + n0 + tx];
    __syncthreads();
    for (int i = 0; i < 32; i += 8) {
        size_t o = mo + (size_t)(n0 + ty + i) * K + k0 + tx;
        hi[o] = __float2half_rn(tile[tx][ty + i]);
    }
}

__global__ void convw_split_kernel(__half* hi, const float* src, int Cin, int total)
{
    int idx = blockIdx.x * 256 + threadIdx.x;
    if (idx >= total) return;
    int K = 3 * Cin;
    int n = idx / K, r = idx - n * K;
    int ks = r / Cin, c = r - ks * Cin;
    hi[idx] = __float2half_rn(src[((size_t)n * Cin + c) * 3 + ks]);
}

__global__ void deconvw_split_kernel(__half* hi, const float* src)
{
    int idx = blockIdx.x * 256 + threadIdx.x;
    int i = blockIdx.y;
    int o = idx / 3072, r = idx - o * 3072;
    int ks = r >> 10, c = r & 1023;
    hi[(size_t)i * 3 * HH + idx] =
        __float2half_rn(src[(size_t)i * 3 * HH + ((size_t)c * 1024 + o) * 3 + ks]);
}

__global__ void deconvw_odd_kernel(__half* hi, const float* src)
{
    int idx = blockIdx.x * 256 + threadIdx.x;
    int l = blockIdx.y;
    int n = idx / 2048, k = idx - n * 2048;
    int ks = (k < 1024) ? 2 : 0;
    int c = k & 1023;
    hi[(size_t)l * 2 * HH + idx] =
        __float2half_rn(src[(size_t)l * 3 * HH + ((size_t)c * 1024 + n) * 3 + ks]);
}

__global__ void deconvw_rev_kernel(__half* hi, const float* src)
{
    int idx = blockIdx.x * 256 + threadIdx.x;
    int n = idx / 3072, k = idx - n * 3072;
    int j = k >> 10, c = k & 1023, ks = 2 - j;
    hi[idx] = __float2half_rn(src[(size_t)2 * 3 * HH + ((size_t)c * 1024 + n) * 3 + ks]);
}

// ---------------- MMA macros ----------------
#define GEMM_SM 61440
#define CP16(d, s) asm volatile("cp.async.ca.shared.global [%0], [%1], 16;" :: "r"(d), "l"(s))
#define LDSM4(r, a) asm volatile( \
    "ldmatrix.sync.aligned.m8n8.x4.shared.b16 {%0,%1,%2,%3}, [%4];" \
    : "=r"((r)[0]), "=r"((r)[1]), "=r"((r)[2]), "=r"((r)[3]) : "r"(a))
#define LDSM4T(r, a) asm volatile( \
    "ldmatrix.sync.aligned.m8n8.x4.trans.shared.b16 {%0,%1,%2,%3}, [%4];" \
    : "=r"((r)[0]), "=r"((r)[1]), "=r"((r)[2]), "=r"((r)[3]) : "r"(a))
#define MMA16(d, A_, B_) asm volatile( \
    "mma.sync.aligned.m16n8k16.row.col.f32.f16.f16.f32 " \
    "{%0,%1,%2,%3},{%4,%5,%6,%7},{%8,%9},{%0,%1,%2,%3};" \
    : "+f"((d)[0]), "+f"((d)[1]), "+f"((d)[2]), "+f"((d)[3]) \
    : "r"((A_)[0]), "r"((A_)[1]), "r"((A_)[2]), "r"((A_)[3]), "r"((B_)[0]), "r"((B_)[1]))

// ---------------- 2-term split GEMM: C = (Ah+Al) @ Bh^T (2-stage) ----------
__device__ __forceinline__ void gemm_body(
    const __half* Ah, const __half* Al, const __half* Bh,
    float* Cf, __half* Ch, __half* Cl, int loN,
    int M, int N, int K, int As_, int Bs_, int aBatch, int apad,
    int rowmul, int rowoff, const float* bias, int relu)
{
    extern __shared__ char smc[];
    const uint32_t smb = (uint32_t)__cvta_generic_to_shared(smc);
    const int t = threadIdx.x, lane = t & 31, wid = t >> 5;
    const int wm = wid & 1, wn = wid >> 1;
    const int bx = blockIdx.x, by = blockIdx.y;

    float acc[4][4][4];
    #pragma unroll
    for (int a = 0; a < 4; a++)
        #pragma unroll
        for (int b = 0; b < 4; b++)
            #pragma unroll
            for (int c = 0; c < 4; c++) acc[a][b][c] = 0.f;

    const __half* P[3] = {Ah, Al, Bh};
    const int KT = K >> 5;

    auto LD = [&](int s, int k0) {
        uint32_t sb = smb + (uint32_t)s * 30720u;
        #pragma unroll
        for (int p = 0; p < 2; p++) {
            #pragma unroll
            for (int i = 0; i < 2; i++) {
                int idx = i * 256 + t, r = idx >> 2, c = idx & 3;
                int g = by * 128 + r;
                int radj = aBatch ? (g + apad * (g / aBatch)) : g;
                CP16(sb + (uint32_t)p * 10240u + (uint32_t)(r * 80 + c * 16),
                     P[p] + (size_t)radj * As_ + k0 + c * 8);
            }
        }
        #pragma unroll
        for (int i = 0; i < 2; i++) {
            int idx = i * 256 + t, r = idx >> 2, c = idx & 3;
            CP16(sb + 20480u + (uint32_t)(r * 80 + c * 16),
                 P[2] + (size_t)(bx * 128 + r) * Bs_ + k0 + c * 8);
        }
    };

    auto COMP = [&](int s) {
        uint32_t sb = smb + (uint32_t)s * 30720u;
        const int arow = wm * 64 + (lane & 7) + ((lane >> 3) & 1) * 8;
        const int brow = wn * 32 + (lane & 7) + ((lane >> 4) & 1) * 8;
        #pragma unroll
        for (int kk = 0; kk < 2; kk++) {
            uint32_t ah[4][4], al[4][4], bh[4][2];
            const int achk = kk * 2 + (lane >> 4);
            const int bchk = kk * 2 + ((lane >> 3) & 1);
            #pragma unroll
            for (int mt = 0; mt < 4; mt++) {
                uint32_t ad = sb + (uint32_t)((arow + mt * 16) * 80 + achk * 16);
                LDSM4(ah[mt], ad);
                LDSM4(al[mt], ad + 10240u);
            }
            #pragma unroll
            for (int np = 0; np < 2; np++) {
                uint32_t bd = sb + 20480u + (uint32_t)((brow + np * 16) * 80 + bchk * 16);
                uint32_t r4[4];
                LDSM4(r4, bd);
                bh[np*2][0] = r4[0]; bh[np*2][1] = r4[1];
                bh[np*2+1][0] = r4[2]; bh[np*2+1][1] = r4[3];
            }
            #pragma unroll
            for (int mt = 0; mt < 4; mt++)
                #pragma unroll
                for (int nt = 0; nt < 4; nt++) {
                    MMA16(acc[mt][nt], ah[mt], bh[nt]);
                    MMA16(acc[mt][nt], al[mt], bh[nt]);
                }
        }
    };

    LD(0, 0);
    asm volatile("cp.async.commit_group;");
    for (int kt = 0; kt < KT; kt++) {
        if (kt + 1 < KT) {
            LD((kt + 1) & 1, (kt + 1) << 5);
            asm volatile("cp.async.commit_group;");
            asm volatile("cp.async.wait_group 1;");
        } else {
            asm volatile("cp.async.wait_group 0;");
        }
        __syncthreads();
        COMP(kt & 1);
        __syncthreads();
    }

    const int lr = lane >> 2, lc = (lane & 3) * 2;
    #pragma unroll
    for (int mt = 0; mt < 4; mt++) {
        int r0 = by * 128 + wm * 64 + mt * 16 + lr;
        int g0 = rowmul * r0 + rowoff;
        int g1 = rowmul * (r0 + 8) + rowoff;
        #pragma unroll
        for (int nt = 0; nt < 4; nt++) {
            int c0 = bx * 128 + wn * 32 + nt * 8 + lc;
            float b0 = 0.f, b1 = 0.f;
            if (bias) { float2 bv = *(const float2*)(bias + c0); b0 = bv.x; b1 = bv.y; }
            float v0 = acc[mt][nt][0] + b0, v1 = acc[mt][nt][1] + b1;
            float v2 = acc[mt][nt][2] + b0, v3 = acc[mt][nt][3] + b1;
            if (relu) { v0 = fmaxf(v0,0.f); v1 = fmaxf(v1,0.f);
                        v2 = fmaxf(v2,0.f); v3 = fmaxf(v3,0.f); }
            size_t o0 = (size_t)g0 * N + c0, o1 = (size_t)g1 * N + c0;
            if (Cf) {
                *(float2*)(Cf + o0) = make_float2(v0, v1);
                *(float2*)(Cf + o1) = make_float2(v2, v3);
            }
            if (Ch) {
                __half2 hh, ll;
                sp2(v0, v1, &hh, &ll);
                *(__half2*)(Ch + o0) = hh;
                if (c0 < loN) *(__half2*)(Cl + o0) = ll;
                sp2(v2, v3, &hh, &ll);
                *(__half2*)(Ch + o1) = hh;
                if (c0 < loN) *(__half2*)(Cl + o1) = ll;
            }
        }
    }
}

__global__ __launch_bounds__(256) void gemm_fp16(
    const __half* Ah, const __half* Al, const __half* Bh,
    float* Cf, __half* Ch, __half* Cl, int loN,
    int M, int N, int K, int As_, int Bs_, int aBatch, int apad,
    int rowmul, int rowoff, const float* bias, int relu)
{
    gemm_body(Ah, Al, Bh, Cf, Ch, Cl, loN, M, N, K, As_, Bs_, aBatch, apad,
              rowmul, rowoff, bias, relu);
}

__global__ __launch_bounds__(256) void gemm_dual(
    const __half* A0h, const __half* A0l, const __half* B0h,
    float* C0f, __half* C0h, __half* C0l, int loN0,
    const __half* A1h, const __half* A1l, const __half* B1h,
    float* C1f, __half* C1h, __half* C1l, int loN1,
    int M, int N, int K)
{
    if (blockIdx.z == 0)
        gemm_body(A0h, A0l, B0h, C0f, C0h, C0l, loN0, M, N, K, K, K, 0, 0, 1, 0, nullptr, 0);
    else
        gemm_body(A1h, A1l, B1h, C1f, C1h, C1l, loN1, M, N, K, K, K, 0, 0, 1, 0, nullptr, 0);
}

// ---------------- flash attention: Q exact, K/V fp16-hi, P exact ----------
#define AT_SM 110592
__device__ __forceinline__ void attn_body(
    const __half* Qh, const __half* Ql, const __half* Kh, const __half* Vh,
    __half* Oh, __half* Ol,
    int S, int windowed, int qstr, int kstr, int qb, int h, int b)
{
    extern __shared__ char smc[];
    const uint32_t sb = (uint32_t)__cvta_generic_to_shared(smc);
    const int t = threadIdx.x, lane = t & 31, w = t >> 5;
    const int lr = lane >> 2, lc = lane & 3;
    const size_t qbase = (size_t)(b * S + qb * 128) * qstr + h * 64;
    const size_t obase = (size_t)(b * S + qb * 128) * 1024 + h * 64;

    for (int i = t; i < 1024; i += 256) {
        int r = i >> 3, c = i & 7;
        size_t go = qbase + (size_t)r * qstr + c * 8;
        uint32_t so = (uint32_t)(r * 144 + c * 16);
        CP16(sb + so,          Qh + go);
        CP16(sb + 18432u + so, Ql + go);
    }
    asm volatile("cp.async.commit_group;");

    const int nb = windowed ? 1 : (S >> 7);
    const int jb0 = windowed ? qb : 0;

    auto ldkv = [&](int jb, int st) {
        uint32_t kb = sb + 36864u + (uint32_t)st * 36864u;
        size_t gb = (size_t)(b * S + jb * 128) * kstr + h * 64;
        for (int i = t; i < 1024; i += 256) {
            int r = i >> 3, c = i & 7;
            size_t go = gb + (size_t)r * kstr + c * 8;
            uint32_t so = (uint32_t)(r * 144 + c * 16);
            CP16(kb + so,           Kh + go);
            CP16(kb + 18432u + so,  Vh + go);
        }
    };

    ldkv(jb0, 0);
    asm volatile("cp.async.commit_group;");
    asm volatile("cp.async.wait_group 1;");
    __syncthreads();

    uint32_t qfh[4][4], qfl[4][4];
    {
        uint32_t qrow = (uint32_t)(w * 16 + (lane & 7) + ((lane >> 3) & 1) * 8);
        #pragma unroll
        for (int kc = 0; kc < 4; kc++) {
            uint32_t qa = sb + qrow * 144u + (uint32_t)((kc * 2 + (lane >> 4)) * 16);
            LDSM4(qfh[kc], qa);
            LDSM4(qfl[kc], qa + 18432u);
        }
    }

    float oacc[8][4];
    #pragma unroll
    for (int j = 0; j < 8; j++)
        #pragma unroll
        for (int c = 0; c < 4; c++) oacc[j][c] = 0.f;
    float m0 = -1e30f, m1 = -1e30f, l0 = 0.f, l1 = 0.f;

    for (int i = 0; i < nb; i++) {
        if (i + 1 < nb) {
            ldkv(jb0 + i + 1, (i + 1) & 1);
            asm volatile("cp.async.commit_group;");
            asm volatile("cp.async.wait_group 1;");
        } else {
            asm volatile("cp.async.wait_group 0;");
        }
        __syncthreads();
        uint32_t kb = sb + 36864u + (uint32_t)(i & 1) * 36864u;

        float sacc[16][4];
        #pragma unroll
        for (int nt = 0; nt < 16; nt++)
            #pragma unroll
            for (int c = 0; c < 4; c++) sacc[nt][c] = 0.f;

        const uint32_t krow = (uint32_t)((lane & 7) + ((lane >> 4) & 1) * 8);
        const uint32_t kchk = (uint32_t)((lane >> 3) & 1);
        #pragma unroll
        for (int np = 0; np < 8; np++) {
            #pragma unroll
            for (int kc = 0; kc < 4; kc++) {
                uint32_t ka = kb + (np * 16 + krow) * 144u + (kc * 2 + kchk) * 16u;
                uint32_t bh4[4];
                LDSM4(bh4, ka);
                MMA16(sacc[2*np],   qfh[kc], &bh4[0]);
                MMA16(sacc[2*np],   qfl[kc], &bh4[0]);
                MMA16(sacc[2*np+1], qfh[kc], &bh4[2]);
                MMA16(sacc[2*np+1], qfl[kc], &bh4[2]);
            }
        }

        float mx0 = -1e30f, mx1 = -1e30f;
        #pragma unroll
        for (int nt = 0; nt < 16; nt++) {
            sacc[nt][0] *= 0.125f; sacc[nt][1] *= 0.125f;
            sacc[nt][2] *= 0.125f; sacc[nt][3] *= 0.125f;
            mx0 = fmaxf(mx0, fmaxf(sacc[nt][0], sacc[nt][1]));
            mx1 = fmaxf(mx1, fmaxf(sacc[nt][2], sacc[nt][3]));
        }
        mx0 = fmaxf(mx0, __shfl_xor_sync(0xffffffffu, mx0, 1));
        mx0 = fmaxf(mx0, __shfl_xor_sync(0xffffffffu, mx0, 2));
        mx1 = fmaxf(mx1, __shfl_xor_sync(0xffffffffu, mx1, 1));
        mx1 = fmaxf(mx1, __shfl_xor_sync(0xffffffffu, mx1, 2));
        float nm0 = fmaxf(m0, mx0), nm1 = fmaxf(m1, mx1);
        float cr0 = __expf(m0 - nm0), cr1 = __expf(m1 - nm1);
        l0 *= cr0; l1 *= cr1;
        #pragma unroll
        for (int j = 0; j < 8; j++) {
            oacc[j][0] *= cr0; oacc[j][1] *= cr0;
            oacc[j][2] *= cr1; oacc[j][3] *= cr1;
        }
        float rs0 = 0.f, rs1 = 0.f;
        #pragma unroll
        for (int nt = 0; nt < 16; nt++) {
            float p0 = __expf(sacc[nt][0] - nm0), p1 = __expf(sacc[nt][1] - nm0);
            float p2 = __expf(sacc[nt][2] - nm1), p3 = __expf(sacc[nt][3] - nm1);
            sacc[nt][0] = p0; sacc[nt][1] = p1; sacc[nt][2] = p2; sacc[nt][3] = p3;
            rs0 += p0 + p1; rs1 += p2 + p3;
        }
        rs0 += __shfl_xor_sync(0xffffffffu, rs0, 1);
        rs0 += __shfl_xor_sync(0xffffffffu, rs0, 2);
        rs1 += __shfl_xor_sync(0xffffffffu, rs1, 1);
        rs1 += __shfl_xor_sync(0xffffffffu, rs1, 2);
        l0 += rs0; l1 += rs1; m0 = nm0; m1 = nm1;

        const uint32_t vrow = (uint32_t)((lane & 7) + ((lane >> 3) & 1) * 8);
        const uint32_t vchk = (uint32_t)((lane >> 4) & 1);
        #pragma unroll
        for (int kc = 0; kc < 8; kc++) {
            uint32_t ph[4], pl[4];
            #pragma unroll
            for (int q = 0; q < 2; q++) {
                __half2 hh, ll;
                sp2(sacc[2*kc+q][0], sacc[2*kc+q][1], &hh, &ll);
                ph[q*2]   = *(uint32_t*)&hh; pl[q*2]   = *(uint32_t*)&ll;
                sp2(sacc[2*kc+q][2], sacc[2*kc+q][3], &hh, &ll);
                ph[q*2+1] = *(uint32_t*)&hh; pl[q*2+1] = *(uint32_t*)&ll;
            }
            #pragma unroll
            for (int p4 = 0; p4 < 4; p4++) {
                uint32_t va = kb + 18432u + (kc * 16 + vrow) * 144u + p4 * 32u + vchk * 16u;
                uint32_t vh4[4];
                LDSM4T(vh4, va);
                MMA16(oacc[2*p4],   ph, &vh4[0]);
                MMA16(oacc[2*p4],   pl, &vh4[0]);
                MMA16(oacc[2*p4+1], ph, &vh4[2]);
                MMA16(oacc[2*p4+1], pl, &vh4[2]);
            }
        }
        __syncthreads();
    }

    const float i0 = 1.f / l0, i1 = 1.f / l1;
    #pragma unroll
    for (int j = 0; j < 8; j++) {
        size_t o0 = obase + (size_t)(w * 16 + lr) * 1024 + j * 8 + lc * 2;
        __half2 hh, ll;
        sp2(oacc[j][0] * i0, oacc[j][1] * i0, &hh, &ll);
        *(__half2*)(Oh + o0) = hh; *(__half2*)(Ol + o0) = ll;
        sp2(oacc[j][2] * i1, oacc[j][3] * i1, &hh, &ll);
        *(__half2*)(Oh + o0 + 8192) = hh; *(__half2*)(Ol + o0 + 8192) = ll;
    }
}

__global__ __launch_bounds__(256) void attn_tc(
    const __half* Qh, const __half* Ql, const __half* Kh, const __half* Vh,
    __half* Oh, __half* Ol, int S, int windowed, int qstr, int kstr)
{
    attn_body(Qh, Ql, Kh, Vh, Oh, Ol, S, windowed, qstr, kstr,
              blockIdx.x, blockIdx.y, blockIdx.z);
}

__global__ __launch_bounds__(256) void attn_tc_dual(
    const __half* Q0h, const __half* Q0l, const __half* K0h, const __half* V0h,
    __half* O0h, __half* O0l,
    const __half* Q1h, const __half* Q1l, const __half* K1h, const __half* V1h,
    __half* O1h, __half* O1l, int S)
{
    int b = blockIdx.z & 3;
    if ((blockIdx.z >> 2) == 0)
        attn_body(Q0h, Q0l, K0h, V0h, O0h, O0l, S, 0, 1024, 2048,
                  blockIdx.x, blockIdx.y, b);
    else
        attn_body(Q1h, Q1l, K1h, V1h, O1h, O1l, S, 0, 1024, 2048,
                  blockIdx.x, blockIdx.y, b);
}

// ---------------- ln / ln_add / pool ----------------
__device__ __forceinline__ float4 ln_row(const float* in1, const float* in2,
                                         const float* g, const float* be,
                                         size_t base, int tid, float* rs, float* rss)
{
    float4 a = *(const float4*)(in1 + base), b2 = *(const float4*)(in2 + base);
    a.x += b2.x; a.y += b2.y; a.z += b2.z; a.w += b2.w;
    float s = a.x + a.y + a.z + a.w;
    float ss = a.x*a.x + a.y*a.y + a.z*a.z + a.w*a.w;
    for (int o = 16; o > 0; o >>= 1) {
        s += __shfl_xor_sync(0xffffffffu, s, o);
        ss += __shfl_xor_sync(0xffffffffu, ss, o);
    }
    if ((tid & 31) == 0) { rs[tid >> 5] = s; rss[tid >> 5] = ss; }
    __syncthreads();
    float st = 0.f, sst = 0.f;
    for (int i = 0; i < 8; i++) { st += rs[i]; sst += rss[i]; }
    const float mean = st * (1.f/1024.f), var = sst * (1.f/1024.f) - mean*mean;
    const float inv = rsqrtf(var + 1e-5f);
    float4 gg = *(const float4*)(g + tid*4), bb = *(const float4*)(be + tid*4), o4;
    o4.x = (a.x-mean)*inv*gg.x + bb.x; o4.y = (a.y-mean)*inv*gg.y + bb.y;
    o4.z = (a.z-mean)*inv*gg.z + bb.z; o4.w = (a.w-mean)*inv*gg.w + bb.w;
    return o4;
}

__global__ __launch_bounds__(256) void ln_kernel(
    float* out, const float* in1, const float* in2, const float* g, const float* be,
    __half* ph, __half* pl)
{
    __shared__ float rs[8], rss[8];
    const int tid = threadIdx.x;
    const size_t base = (size_t)blockIdx.x * 1024 + tid * 4;
    float4 o4 = ln_row(in1, in2, g, be, base, tid, rs, rss);
    *(float4*)(out + base) = o4;
    if (ph) {
        __half2 hh, ll;
        sp2(o4.x, o4.y, &hh, &ll);
        *(__half2*)(ph + base) = hh; *(__half2*)(pl + base) = ll;
        sp2(o4.z, o4.w, &hh, &ll);
        *(__half2*)(ph + base + 2) = hh; *(__half2*)(pl + base + 2) = ll;
    }
}

__global__ __launch_bounds__(256) void ln_add_dual(
    float* out, __half* ph, __half* pl,
    const float* fe, const float* bT, const float* g0, const float* e0,
    const float* fd, const float* bT2, const float* g1, const float* e1)
{
    __shared__ float rs[8], rss[8];
    const int tid = threadIdx.x;
    const size_t base = (size_t)blockIdx.x * 1024 + tid * 4;
    float4 x2 = ln_row(fe, bT, g0, e0, base, tid, rs, rss);
    __syncthreads();
    float4 y2 = ln_row(fd, bT2, g1, e1, base, tid, rs, rss);
    float4 o4 = make_float4(x2.x + y2.x, x2.y + y2.y, x2.z + y2.z, x2.w + y2.w);
    *(float4*)(out + base) = o4;
    __half2 hh, ll;
    sp2(o4.x, o4.y, &hh, &ll);
    *(__half2*)(ph + base) = hh; *(__half2*)(pl + base) = ll;
    sp2(o4.z, o4.w, &hh, &ll);
    *(__half2*)(ph + base + 2) = hh; *(__half2*)(pl + base + 2) = ll;
}

__global__ void poolrelu_kernel(float* out, __half* ph, __half* pl,
                                const float* in, int S2, int n4)
{
    int idx = blockIdx.x * blockDim.x + threadIdx.x;
    if (idx >= n4) return;
    int h4 = idx & 255, bt = idx >> 8, b = bt / S2, t2 = bt - b * S2;
    const float4* i0 = (const float4*)in + ((size_t)(b*S2*2 + t2*2) * 256 + h4);
    float4 a = i0[0], c = i0[256], o;
    o.x = fmaxf(fmaxf(a.x,c.x),0.f); o.y = fmaxf(fmaxf(a.y,c.y),0.f);
    o.z = fmaxf(fmaxf(a.z,c.z),0.f); o.w = fmaxf(fmaxf(a.w,c.w),0.f);
    ((float4*)out)[idx] = o;
    size_t base = (size_t)idx * 4;
    __half2 hh, ll;
    sp2(o.x, o.y, &hh, &ll);
    *(__half2*)(ph + base) = hh; *(__half2*)(pl + base) = ll;
    sp2(o.z, o.w, &hh, &ll);
    *(__half2*)(ph + base + 2) = hh; *(__half2*)(pl + base + 2) = ll;
}

// ---------------- host ----------------
extern "C" void kernel_launch(void* const* d_in, const int* in_sizes, int n_in,
                              void* d_out, int out_size)
{
    (void)in_sizes; (void)n_in; (void)out_size;
    const float* x        = (const float*)d_in[0];
    const float* emb_w    = (const float*)d_in[1];
    const float* emb_b    = (const float*)d_in[2];
    const float* enc_qkvo = (const float*)d_in[3];
    const float* enc_ln   = (const float*)d_in[4];
    const float* ef1      = (const float*)d_in[5];
    const float* eb1      = (const float*)d_in[6];
    const float* ef2      = (const float*)d_in[7];
    const float* eb2      = (const float*)d_in[8];
    const float* conv0_w  = (const float*)d_in[9];
    const float* conv0_b  = (const float*)d_in[10];
    const float* dq0      = (const float*)d_in[11];
    const float* dln0     = (const float*)d_in[12];
    const float* da1      = (const float*)d_in[13];
    const float* da2      = (const float*)d_in[14];
    const float* dln      = (const float*)d_in[15];
    const float* df1      = (const float*)d_in[16];
    const float* db1      = (const float*)d_in[17];
    const float* df2      = (const float*)d_in[18];
    const float* db2      = (const float*)d_in[19];
    const float* ddw      = (const float*)d_in[20];
    const float* ddb      = (const float*)d_in[21];

    __half *W, *im, *As, *Zs, *at;
    float *buf;
    cudaGetSymbolAddress((void**)&W,  g_W);
    cudaGetSymbolAddress((void**)&im, g_im);
    cudaGetSymbolAddress((void**)&As, g_As);
    cudaGetSymbolAddress((void**)&Zs, g_Zs);
    cudaGetSymbolAddress((void**)&at, g_at);
    cudaGetSymbolAddress((void**)&buf, g_buf);

    float *bX = buf, *bT = buf+(size_t)20*HH, *bY = buf+(size_t)24*HH,
          *bD = buf+(size_t)28*HH, *bZ = buf+(size_t)36*HH, *bT2 = buf+(size_t)40*HH;
    __half *Ash = As, *Asl = As + ASLO, *imL = im + IMLO;
    __half *Zsh = Zs, *Zsl = Zs + ZSLO;
    __half *fdph = im + (size_t)20*HH, *fdpl = im + IMLO + (size_t)20*HH;
    __half *Q0h = at,                 *Q0l = at + (size_t)4*HH,
           *KV0h = at + (size_t)8*HH,
           *A0h = at + (size_t)24*HH,  *A0l = at + (size_t)28*HH,
           *Q1h = at + (size_t)32*HH,  *Q1l = at + (size_t)36*HH,
           *KV1h = at + (size_t)40*HH,
           *A1h = at + (size_t)56*HH,  *A1l = at + (size_t)60*HH;
    __half *QKVh = at, *QKVl = at + (size_t)12*HH;

    const size_t oE = 0, oD0 = (size_t)16*HH, oD1 = (size_t)20*HH, oD2 = (size_t)32*HH,
                 oF1e = (size_t)44*HH, oF2e = (size_t)60*HH, oF1d = (size_t)76*HH,
                 oF2d = (size_t)88*HH, oWe = (size_t)100*HH,
                 oWc = oWe + 7077888, oWd = oWc + (size_t)3*HH,
                 oWdO = oWd + (size_t)9*HH, oWdR = oWdO + (size_t)4*HH;
    const size_t zo[4] = {0, 4194304, 8388608, 10485760};

    float* out = (float*)d_out;
    float* Z0 = out;                      float* Z1 = out + (size_t)4194304;
    float* Z2 = out + (size_t)8388608;    float* Z3 = out + (size_t)10485760;
    float* FD0 = out + (size_t)11534336;  float* FD1 = out + (size_t)12582912;
    float* FD2 = out + (size_t)14680064;  float* FD3 = out + (size_t)18874368;

    cudaFuncSetAttribute(attn_tc, cudaFuncAttributeMaxDynamicSharedMemorySize, AT_SM);
    cudaFuncSetAttribute(attn_tc_dual, cudaFuncAttributeMaxDynamicSharedMemorySize, AT_SM);
    cudaFuncSetAttribute(gemm_fp16, cudaFuncAttributeMaxDynamicSharedMemorySize, GEMM_SM);
    cudaFuncSetAttribute(gemm_dual, cudaFuncAttributeMaxDynamicSharedMemorySize, GEMM_SM);

    auto GE = [&](const __half* ah, const __half* al, size_t ow,
                  float* Cf, __half* Ch, __half* Cl, int loN,
                  int M, int N, int K, const float* bias, int relu) {
        gemm_fp16<<<dim3(N/128, M/128), 256, GEMM_SM>>>(ah, al, W + ow,
            Cf, Ch, Cl, loN, M, N, K, K, K, 0, 0, 1, 0, bias, relu);
    };
    auto GEc = [&](const __half* ah, const __half* al, int As_, int aB, int apad,
                   size_t bo, int Bs_, float* Cf, __half* Ch, __half* Cl,
                   int M, int N, int K, int rm, int ro, const float* bias, int relu) {
        gemm_fp16<<<dim3(N/128, M/128), 256, GEMM_SM>>>(ah, al, W + bo,
            Cf, Ch, Cl, N, M, N, K, As_, Bs_, aB, apad, rm, ro, bias, relu);
    };
    auto GE2 = [&](const __half* a0h, const __half* a0l, size_t w0,
                   float* c0f, __half* c0h, __half* c0l, int loN0,
                   const __half* a1h, const __half* a1l, size_t w1,
                   float* c1f, __half* c1h, __half* c1l, int loN1,
                   int M, int N, int K) {
        gemm_dual<<<dim3(N/128, M/128, 2), 256, GEMM_SM>>>(
            a0h, a0l, W + w0, c0f, c0h, c0l, loN0,
            a1h, a1l, W + w1, c1f, c1h, c1l, loN1, M, N, K);
    };

    // ---- prep ----
    dim3 b32(32, 8);
    transpose_split_pad<<<dim3(32, 72, 4), b32>>>(im, imL, x);
    zero_embpad<<<9, 256>>>(im, imL);
    convw_split_kernel<<<27648, 256>>>(W + oWe, emb_w, 2304, 7077888);
    wsplit4_kernel<<<dim3(32, 32, 44), b32>>>(W + oE, enc_qkvo, dq0, da1, da2);
    wsplit_kernel<<<dim3(128, 32, 4), b32>>>(W + oF1e, ef1, 1024, 4096);
    wsplit_kernel<<<dim3(32, 128, 4), b32>>>(W + oF2e, ef2, 4096, 1024);
    wsplit_kernel<<<dim3(128, 32, 3), b32>>>(W + oF1d, df1, 1024, 4096);
    wsplit_kernel<<<dim3(32, 128, 3), b32>>>(W + oF2d, df2, 4096, 1024);
    convw_split_kernel<<<12288, 256>>>(W + oWc, conv0_w, 1024, 3*HH);
    deconvw_split_kernel<<<dim3(12288, 3), 256>>>(W + oWd, ddw);
    deconvw_odd_kernel<<<dim3(8192, 2), 256>>>(W + oWdO, ddw);
    deconvw_rev_kernel<<<12288, 256>>>(W + oWdR, ddw);

    GEc(im, imL, 2304, 1024, 2, oWe, 6912, bX, Ash, Asl, 4096, 1024, 6912, 1, 0, emb_b, 1);

    auto mhaSelf = [&](const __half* xh, const __half* xl, size_t ow, int S, int wnd) {
        int rows = 4 * S;
        GE(xh, xl, ow, nullptr, QKVh, QKVl, 1024, rows, 3072, 1024, nullptr, 0);
        attn_tc<<<dim3(S/128, 16, 4), 256, AT_SM>>>(
            QKVh, QKVl, QKVh + 1024, QKVh + 2048,
            A0h, A0l, S, wnd, 3072, 3072);
        GE(A0h, A0l, ow + (size_t)3*HH, bT, nullptr, nullptr, 0, rows, 1024, 1024, nullptr, 0);
    };

    const int encS[4] = {1024, 1024, 512, 256};
    float* Zp[4] = {Z0, Z1, Z2, Z3};
    for (int i = 0; i < 4; i++) {
        int S = encS[i], rows = 4 * S;
        mhaSelf(Ash, Asl, oE + (size_t)i*4*HH, S, 1);
        const float* lnb = enc_ln + (size_t)i * 4096;
        ln_kernel<<<rows, 256>>>(bY, bX, bT, lnb, lnb + 1024, Ash, Asl);
        GE(Ash, Asl, oF1e + (size_t)i*4*HH, nullptr, im, imL, 4096, rows, 4096, 1024,
           eb1 + (size_t)i*4096, 1);
        GE(im, imL, oF2e + (size_t)i*4*HH, bT, nullptr, nullptr, 0, rows, 1024, 4096,
           eb2 + (size_t)i*1024, 0);
        ln_kernel<<<rows, 256>>>(Zp[i], bY, bT, lnb + 2048, lnb + 3072,
                                 Zsh + zo[i], Zsl + zo[i]);
        if (i == 0) {
            pad_planes<<<(4*1026*128 + 255)/256, 256>>>(im, imL, Zsh + zo[0], Zsl + zo[0],
                                                        1024, 1, 1, 4*1026*128);
            GEc(im, imL, 1024, 1024, 2, oWc, 3072, bX, Ash, Asl, rows, 1024, 3072, 1, 0,
                conv0_b, 1);
        } else if (i < 3) {
            int S2 = S/2, n4 = 4*S2*256;
            poolrelu_kernel<<<(n4 + 255)/256, 256>>>(bX, Ash, Asl, Zp[i], S2, n4);
        }
    }

    mhaSelf(Zsh + zo[3], Zsl + zo[3], oD0, 256, 0);
    ln_kernel<<<1024, 256>>>(FD0, Z3, bT, dln0, dln0 + 1024, fdph, fdpl);

    const float* fdPrev = FD0; int Sprev = 256;
    const float* feP[3] = {Z2, Z1, Z0};
    const size_t feZ[3] = {zo[2], zo[1], zo[0]};
    const int decS[3] = {512, 1024, 1024}, decSt[3] = {2, 2, 1};
    float* fdOut[3] = {FD1, FD2, FD3};
    for (int i = 0; i < 3; i++) {
        int S = decS[i], rows = 4 * S;
        if (decSt[i] == 2) {
            int n8 = 4*(Sprev+1)*128;
            pad_planes<<<(n8 + 255)/256, 256>>>(im, imL, fdph, fdpl, Sprev, 0, 1, n8);
            GEc(fdph, fdpl, 1024, 0, 0, oWd + (size_t)i*3*HH + 1024, 3072,
                bD, Ash, Asl, rows/2, 1024, 1024, 2, 0, ddb + (size_t)i*1024, 1);
            GEc(im, imL, 1024, Sprev, 1, oWdO + (size_t)i*2*HH, 2048,
                bD, Ash, Asl, rows/2, 1024, 2048, 2, 1, ddb + (size_t)i*1024, 1);
        } else {
            int n8 = 4*(Sprev+2)*128;
            pad_planes<<<(n8 + 255)/256, 256>>>(im, imL, fdph, fdpl, Sprev, 1, 1, n8);
            GEc(im, imL, 1024, 1024, 2, oWdR, 3072,
                bD, Ash, Asl, rows, 1024, 3072, 1, 0, ddb + (size_t)i*1024, 1);
        }
        const float* lnb = dln + (size_t)i * 6144;
        const size_t a1 = oD1 + (size_t)i*4*HH, a2 = oD2 + (size_t)i*4*HH;
        GE2(Zsh + feZ[i], Zsl + feZ[i], a1, nullptr, Q0h, Q0l, 1024,
            Ash, Asl,                   a2, nullptr, Q1h, Q1l, 1024, rows, 1024, 1024);
        GE2(Ash, Asl,                   a1 + (size_t)HH, nullptr, KV0h, nullptr, 0,
            Zsh + feZ[i], Zsl + feZ[i], a2 + (size_t)HH, nullptr, KV1h, nullptr, 0,
            rows, 2048, 1024);
        attn_tc_dual<<<dim3(S/128, 16, 8), 256, AT_SM>>>(
            Q0h, Q0l, KV0h, KV0h + 1024, A0h, A0l,
            Q1h, Q1l, KV1h, KV1h + 1024, A1h, A1l, S);
        GE2(A0h, A0l, a1 + (size_t)3*HH, bT,  nullptr, nullptr, 0,
            A1h, A1l, a2 + (size_t)3*HH, bT2, nullptr, nullptr, 0, rows, 1024, 1024);
        ln_add_dual<<<rows, 256>>>(bZ, Ash, Asl, feP[i], bT, lnb, lnb + 1024,
                                   bD, bT2, lnb + 2048, lnb + 3072);
        GE(Ash, Asl, oF1d + (size_t)i*4*HH, nullptr, im, imL, 4096, rows, 4096, 1024,
           db1 + (size_t)i*4096, 1);
        GE(im, imL, oF2d + (size_t)i*4*HH, bT, nullptr, nullptr, 0, rows, 1024, 4096,
           db2 + (size_t)i*1024, 0);
        ln_kernel<<<rows, 256>>>(fdOut[i], bZ, bT, lnb + 4096, lnb + 5120, fdph, fdpl);
        fdPrev = fdOut[i]; Sprev = S;
    }
    (void)fdPrev;
}